// round 13
// baseline (speedup 1.0000x reference)
#include <cuda_runtime.h>
#include <cstdint>

#define VOCAB 50000
#define EMB   32
#define HID   64
#define H4    256
#define NCLS  3
#define BSZ   512
#define TLEN  512
#define FULL  0xffffffffu

// h smem layout: batch stride 80 floats (STS banks disjoint), buffer stride 160
#define HS_S  80
#define HS_B  160

// 51.2MB scratch: precomputed emb @ Wk + bias, per vocab entry (256 floats each)
__device__ float g_table[(size_t)VOCAB * H4];

// ---------- packed f32x2 helpers (sm_103a FFMA2 path, PTX-only) ----------
__device__ __forceinline__ unsigned long long pack2(float lo, float hi) {
    unsigned long long r;
    asm("mov.b64 %0, {%1, %2};" : "=l"(r) : "f"(lo), "f"(hi));
    return r;
}
__device__ __forceinline__ float2 unpack2(unsigned long long v) {
    float2 f;
    asm("mov.b64 {%0, %1}, %2;" : "=f"(f.x), "=f"(f.y) : "l"(v));
    return f;
}
#define FMA2(acc, a, b) \
    asm("fma.rn.f32x2 %0, %1, %2, %0;" : "+l"(acc) : "l"(a), "l"(b))
#define ADD2(d, a, b) \
    asm("add.rn.f32x2 %0, %1, %2;" : "=l"(d) : "l"(a), "l"(b))

__device__ __forceinline__ float ex2a(float x) {
    float r;
    asm("ex2.approx.ftz.f32 %0, %1;" : "=f"(r) : "f"(x));
    return r;
}
__device__ __forceinline__ float rcpa(float x) {
    float r;
    asm("rcp.approx.ftz.f32 %0, %1;" : "=f"(r) : "f"(x));
    return r;
}
#define LOG2E  1.4426950408889634f
#define LOG2E2 2.8853900817779268f

// ---------- kernel 1: g_table[v][j] = sum_e emb[v][e]*Wk[e][j] + b[j] ----------
// 2 columns per thread, STG.64 stores (R9, kept).
__global__ __launch_bounds__(256) void table_kernel(
    const float* __restrict__ emb, const float* __restrict__ Wk,
    const float* __restrict__ bias)
{
    __shared__ __align__(16) float sh_e[64 * EMB];
    const int tid = threadIdx.x;
    const int c0  = (tid & 127) * 2;
    const int rg  = tid >> 7;
    const int v0  = blockIdx.x * 64;

    unsigned long long wkA[16], wkB[16];
#pragma unroll
    for (int m = 0; m < 16; m++) {
        wkA[m] = pack2(Wk[(2 * m) * H4 + c0],     Wk[(2 * m + 1) * H4 + c0]);
        wkB[m] = pack2(Wk[(2 * m) * H4 + c0 + 1], Wk[(2 * m + 1) * H4 + c0 + 1]);
    }
    const float bA = bias[c0], bB = bias[c0 + 1];

    const int nrows = min(64, VOCAB - v0);
    const float4* src = reinterpret_cast<const float4*>(emb + (size_t)v0 * EMB);
    float4* dst = reinterpret_cast<float4*>(sh_e);
    for (int i = tid; i < nrows * (EMB / 4); i += 256) dst[i] = src[i];
    __syncthreads();

    const int r_lo = rg * 32;
    const int r_hi = min(r_lo + 32, nrows);
    for (int r = r_lo; r < r_hi; r++) {
        const ulonglong2* ev = reinterpret_cast<const ulonglong2*>(sh_e + r * EMB);
        unsigned long long a0 = 0ull, a1 = 0ull, b0 = 0ull, b1 = 0ull;
#pragma unroll
        for (int m = 0; m < 8; m++) {
            ulonglong2 p = ev[m];
            FMA2(a0, p.x, wkA[2 * m]);
            FMA2(a1, p.y, wkA[2 * m + 1]);
            FMA2(b0, p.x, wkB[2 * m]);
            FMA2(b1, p.y, wkB[2 * m + 1]);
        }
        unsigned long long sa, sb;
        ADD2(sa, a0, a1);
        ADD2(sb, b0, b1);
        float2 fa = unpack2(sa), fb = unpack2(sb);
        float2 o;
        o.x = bA + fa.x + fa.y;
        o.y = bB + fb.x + fb.y;
        *reinterpret_cast<float2*>(&g_table[(size_t)(v0 + r) * H4 + c0]) = o;
    }
}

// ---------- kernel 2: recurrent LSTM, 2 batch rows per CTA, occ 2 ----------
// Gate-split pair ownership (R12) + two-phase batch pipeline (R13):
//   phase 0: batch-0 dots -> shfl -> EVEN lanes gate batch0 + STS h
//            (gate MUFU chain retires under the phase-1 FMA block)
//   phase 1: batch-1 dots -> shfl -> ODD lanes gate batch1 + STS h
//            (xz prefetch LDGs fill even lanes' window)
// ONE CTA barrier per step. Double-buffered h; fused-rcp gates; anti-phase
// stagger on odd CTAs.
__global__ __launch_bounds__(128, 2) void lstm_kernel(
    const int*   __restrict__ tokens,
    const float* __restrict__ Wr,
    const float* __restrict__ Wd,
    const float* __restrict__ bd,
    float*       __restrict__ out)
{
    __shared__ __align__(16) float sh_h[2 * HS_B];   // [buf(160)][batch(80)][unit]
    __shared__ int   sh_tok[2][TLEN + 1];
    __shared__ float sh_sink;

    const int j   = threadIdx.x;          // 0..127
    const int u   = j >> 1;               // unit 0..63
    const int par = j & 1;                // 0: i/g cols, gates batch0; 1: f/o, batch1
    const int cA  = u + par * 64;         // i (even) / f (odd)
    const int cB  = u + 128 + par * 64;   // g (even) / o (odd)
    const int b0  = blockIdx.x * 2;

    // stage this CTA's 2 token rows (+1 pad so prefetch needs no clamp)
    for (int i = j; i < 2 * TLEN; i += 128) {
        int s = i >> 9, t = i & (TLEN - 1);
        sh_tok[s][t] = tokens[(size_t)(b0 + s) * TLEN + t];
    }
    if (j < 2) sh_tok[j][TLEN] = tokens[(size_t)(b0 + j) * TLEN + (TLEN - 1)];

    // Wr columns cA, cB packed over k (64 b64 = 128 regs)
    unsigned long long wA[32], wB[32];
#pragma unroll
    for (int m = 0; m < 32; m++) {
        wA[m] = pack2(Wr[(2 * m) * H4 + cA], Wr[(2 * m + 1) * H4 + cA]);
        wB[m] = pack2(Wr[(2 * m) * H4 + cB], Wr[(2 * m + 1) * H4 + cB]);
    }

    sh_h[0 * HS_B + par * HS_S + u] = 0.0f;  // 128 threads cover [2][64]
    float cst = 0.0f;                        // cell state for (par, u)

    // anti-phase stagger: odd CTAs burn ~700 cyc (R6 win, kept)
    if (blockIdx.x & 1) {
        float d = (float)(sh_tok[0][0] & 1);
        const float z0c = 0.0f;
#pragma unroll 1
        for (int i = 0; i < 128; i++)
            asm("add.f32 %0, %0, %1;" : "+f"(d) : "f"(z0c));
        if (d > 2.0f) sh_sink = d;  // never true; keeps chain alive
    }
    __syncthreads();

    // prefetch xz for t=0: cols cA, cB for both batches
    float xzA0 = g_table[(size_t)sh_tok[0][0] * H4 + cA];
    float xzB0 = g_table[(size_t)sh_tok[0][0] * H4 + cB];
    float xzA1 = g_table[(size_t)sh_tok[1][0] * H4 + cA];
    float xzB1 = g_table[(size_t)sh_tok[1][0] * H4 + cB];

#pragma unroll 1
    for (int t = 0; t < TLEN; t++) {
        const int  wrbuf = ((t & 1) ^ 1) * HS_B;
        const float* hb  = sh_h + (t & 1) * HS_B;
        const ulonglong2* h0 = reinterpret_cast<const ulonglong2*>(hb);
        const ulonglong2* h1 = reinterpret_cast<const ulonglong2*>(hb + HS_S);

        // ---- phase 0: batch-0 dots ----
        unsigned long long p0A = pack2(xzA0, 0.0f), p0A1 = 0ull;
        unsigned long long p0B = pack2(xzB0, 0.0f), p0B1 = 0ull;
#pragma unroll
        for (int m = 0; m < 16; m++) {
            ulonglong2 p = h0[m];
            FMA2(p0A,  p.x, wA[2 * m]);
            FMA2(p0A1, p.y, wA[2 * m + 1]);
            FMA2(p0B,  p.x, wB[2 * m]);
            FMA2(p0B1, p.y, wB[2 * m + 1]);
        }
        float zA0, zB0;
        {
            unsigned long long r;
            float2 f;
            ADD2(r, p0A, p0A1); f = unpack2(r); zA0 = f.x + f.y;
            ADD2(r, p0B, p0B1); f = unpack2(r); zB0 = f.x + f.y;
        }
        // exchange batch-0 pair: even lane receives odd's (f,o)
        const unsigned long long rx0 = __shfl_xor_sync(FULL, pack2(zA0, zB0), 1);

        // EVEN lanes gate batch0 now; chain retires under phase-1 FMA
        if (par == 0) {
            const float2 rv = unpack2(rx0);
            const float ei = ex2a(-LOG2E * zA0);    // i
            const float ef = ex2a(-LOG2E * rv.x);   // f
            const float eg = ex2a(-LOG2E2 * zB0);   // g
            const float eo = ex2a(-LOG2E * rv.y);   // o
            const float fg = rcpa(1.0f + ef);
            const float r1 = rcpa((1.0f + ei) * (1.0f + eg));
            cst = fmaf(fg, cst, (1.0f - eg) * r1);
            const float ec = ex2a(-LOG2E2 * cst);
            const float r2 = rcpa((1.0f + eo) * (1.0f + ec));
            sh_h[wrbuf + u] = (1.0f - ec) * r2;     // batch 0
        }

        // ---- phase 1: batch-1 dots ----
        unsigned long long p1A = pack2(xzA1, 0.0f), p1A1 = 0ull;
        unsigned long long p1B = pack2(xzB1, 0.0f), p1B1 = 0ull;
#pragma unroll
        for (int m = 0; m < 16; m++) {
            ulonglong2 p = h1[m];
            FMA2(p1A,  p.x, wA[2 * m]);
            FMA2(p1A1, p.y, wA[2 * m + 1]);
            FMA2(p1B,  p.x, wB[2 * m]);
            FMA2(p1B1, p.y, wB[2 * m + 1]);
        }
        float zA1v, zB1v;
        {
            unsigned long long r;
            float2 f;
            ADD2(r, p1A, p1A1); f = unpack2(r); zA1v = f.x + f.y;
            ADD2(r, p1B, p1B1); f = unpack2(r); zB1v = f.x + f.y;
        }
        // exchange batch-1 pair: odd lane receives even's (i,g)
        const unsigned long long rx1 = __shfl_xor_sync(FULL, pack2(zA1v, zB1v), 1);

        // prefetch next step's xz (fills even lanes' idle window)
        const int tk0 = sh_tok[0][t + 1], tk1 = sh_tok[1][t + 1];
        xzA0 = g_table[(size_t)tk0 * H4 + cA];
        xzB0 = g_table[(size_t)tk0 * H4 + cB];
        xzA1 = g_table[(size_t)tk1 * H4 + cA];
        xzB1 = g_table[(size_t)tk1 * H4 + cB];

        // ODD lanes gate batch1
        if (par == 1) {
            const float2 rv = unpack2(rx1);
            const float ei = ex2a(-LOG2E * rv.x);    // i
            const float ef = ex2a(-LOG2E * zA1v);    // f
            const float eg = ex2a(-LOG2E2 * rv.y);   // g
            const float eo = ex2a(-LOG2E * zB1v);    // o
            const float fg = rcpa(1.0f + ef);
            const float r1 = rcpa((1.0f + ei) * (1.0f + eg));
            cst = fmaf(fg, cst, (1.0f - eg) * r1);
            const float ec = ex2a(-LOG2E2 * cst);
            const float r2 = rcpa((1.0f + eo) * (1.0f + ec));
            sh_h[wrbuf + HS_S + u] = (1.0f - ec) * r2;   // batch 1
        }

        __syncthreads();  // single barrier: h published, buffers swap
    }

    // final h in buffer 0 (last write at t=511 targets (511&1)^1 = 0)
    if (j < 2) {
        const int s = j;
        const float* hrow = sh_h + s * HS_S;
        float l0 = bd[0], l1 = bd[1], l2 = bd[2];
#pragma unroll 8
        for (int uu = 0; uu < HID; uu++) {
            const float h = hrow[uu];
            l0 += h * Wd[uu * NCLS + 0];
            l1 += h * Wd[uu * NCLS + 1];
            l2 += h * Wd[uu * NCLS + 2];
        }
        const float m  = fmaxf(l0, fmaxf(l1, l2));
        const float e0 = ex2a(LOG2E * (l0 - m));
        const float e1 = ex2a(LOG2E * (l1 - m));
        const float e2 = ex2a(LOG2E * (l2 - m));
        const float inv = rcpa(e0 + e1 + e2);
        float* o = out + (size_t)(b0 + s) * NCLS;
        o[0] = e0 * inv;
        o[1] = e1 * inv;
        o[2] = e2 * inv;
    }
}

extern "C" void kernel_launch(void* const* d_in, const int* in_sizes, int n_in,
                              void* d_out, int out_size)
{
    const int*   tokens = (const int*)  d_in[0];
    const float* emb    = (const float*)d_in[1];
    const float* Wk     = (const float*)d_in[2];
    const float* Wr     = (const float*)d_in[3];
    const float* b      = (const float*)d_in[4];
    const float* Wd     = (const float*)d_in[5];
    const float* bd     = (const float*)d_in[6];
    float* out = (float*)d_out;

    table_kernel<<<(VOCAB + 63) / 64, 256>>>(emb, Wk, b);
    lstm_kernel<<<BSZ / 2, 128>>>(tokens, Wr, Wd, bd, out);
}